// round 10
// baseline (speedup 1.0000x reference)
#include <cuda_runtime.h>
#include <cstdint>
#include <cstddef>

#define Bb 32
#define Dd 256
#define Ll 4096
#define Kk 1024
#define Nn (Bb*Ll)            // 131072 rows
#define NDL (Bb*Dd*Ll)        // 33554432 z_q elements
#define TL 32                 // l-tile for gather

__device__ int    g_idx[Nn];
__device__ float  g_enorm[Kk];
__device__ double g_acc;

// ---------------------------------------------------------------------------
// smem layout (bytes): zs[256][132] | es[128][132] | en[1024] | zn[128]
// ---------------------------------------------------------------------------
#define ZST 132
#define EST 132
#define SM_ZS 0
#define SM_ES (256*ZST*4)              // 135168
#define SM_EN (SM_ES + 128*EST*4)      // 202752
#define SM_ZN (SM_EN + 4096)           // 206848
#define SM_TOTAL (SM_ZN + 512)         // 207360

// ---------------------------------------------------------------------------
// packed f32x2 helpers
// ---------------------------------------------------------------------------
__device__ __forceinline__ void fma_x2(uint64_t& c, uint64_t a, uint64_t b) {
    asm("fma.rn.f32x2 %0, %1, %2, %0;" : "+l"(c) : "l"(a), "l"(b));
}
__device__ __forceinline__ uint64_t dup_x2(float x) {
    uint64_t r;
    asm("mov.b64 %0, {%1, %1};" : "=l"(r) : "f"(x));
    return r;
}
__device__ __forceinline__ void unpack_x2(float& lo, float& hi, uint64_t v) {
    asm("mov.b64 {%0, %1}, %2;" : "=f"(lo), "=f"(hi) : "l"(v));
}
__device__ __forceinline__ void lds_v2u64(uint64_t& a, uint64_t& b, const void* p) {
    asm volatile("ld.shared.v2.b64 {%0, %1}, [%2];"
                 : "=l"(a), "=l"(b) : "l"(__cvta_generic_to_shared(p)));
}
__device__ __forceinline__ void lds_v4f32(float& a, float& b, float& c, float& d,
                                          const void* p) {
    asm volatile("ld.shared.v4.f32 {%0, %1, %2, %3}, [%4];"
                 : "=f"(a), "=f"(b), "=f"(c), "=f"(d)
                 : "l"(__cvta_generic_to_shared(p)));
}

// ---------------------------------------------------------------------------
// prep: per-code squared norms + zero loss accumulator
// ---------------------------------------------------------------------------
__global__ void vq_prep_kernel(const float* __restrict__ emb) {
    int k = blockIdx.x * blockDim.x + threadIdx.x;
    if (k == 0) g_acc = 0.0;
    if (k < Kk) {
        const float* row = emb + (size_t)k * Dd;
        float s = 0.f;
        #pragma unroll 8
        for (int d = 0; d < Dd; d++) { float v = row[d]; s += v * v; }
        g_enorm[k] = s;
    }
}

// ---------------------------------------------------------------------------
// scores: exact fp32 distances via packed fma.rn.f32x2 (FFMA2), fused argmin.
// 512 threads; CTA = 128 rows x 1024 codes in 8 k-tiles of 128;
// thread = 8 rows (4 f32x2 pairs) x 4 codes.
// Arithmetic identical to the reference-matching R1/R7 kernels:
//   one sequential fp32 FMA chain over ascending d per (row, code),
//   dist = (||z||^2 + ||e||^2) - 2*acc, ascending-k strict-< argmin.
// ---------------------------------------------------------------------------
__global__ void __launch_bounds__(512, 1)
vq_scores_f32x2(const float* __restrict__ z, const float* __restrict__ emb) {
    extern __shared__ char smem[];
    float* zs   = (float*)(smem + SM_ZS);   // [256][ZST] z transposed: [d][row]
    float* es   = (float*)(smem + SM_ES);   // [128][EST] e chunk: [dd][k]
    float* s_en = (float*)(smem + SM_EN);
    float* s_zn = (float*)(smem + SM_ZN);

    const int tid  = threadIdx.x;
    const int lane = tid & 31;      // code-group: 4 codes each (k-tile = 128)
    const int rg   = tid >> 5;      // row-group (= warp): 8 rows each
    const int r0   = rg * 8;
    const int k0   = lane * 4;

    const int row0 = blockIdx.x * 128;
    const int b    = row0 >> 12;
    const int l0   = row0 & (Ll - 1);
    const float* zb = z + (size_t)b * Dd * Ll + l0;

    // stage z transposed zs[d][l]: coalesced float4 LDG, conflict-free STS.128
    #pragma unroll
    for (int i = 0; i < 16; i++) {
        int idx = i * 512 + tid;
        int l4  = (idx & 31) * 4;
        int d   = idx >> 5;
        float4 v = *(const float4*)&zb[(size_t)d * Ll + l4];
        *(float4*)&zs[d * ZST + l4] = v;
    }
    for (int i = tid; i < Kk; i += 512) s_en[i] = g_enorm[i];
    __syncthreads();

    // per-row ||z||^2: sequential fp32 chain over ascending d
    if (tid < 128) {
        float s = 0.f;
        #pragma unroll 8
        for (int d = 0; d < Dd; d++) { float v = zs[d * ZST + tid]; s += v * v; }
        s_zn[tid] = s;
    }
    __syncthreads();

    float zr[8];
    #pragma unroll
    for (int j = 0; j < 8; j++) zr[j] = s_zn[r0 + j];

    float bv[8];
    int   bi[8];
    #pragma unroll
    for (int j = 0; j < 8; j++) { bv[j] = 3.4e38f; bi[j] = 0; }

    #pragma unroll 1
    for (int kt = 0; kt < 8; kt++) {
        uint64_t acc[4][4];           // [row-pair][code]
        #pragma unroll
        for (int p = 0; p < 4; p++)
            #pragma unroll
            for (int c = 0; c < 4; c++) acc[p][c] = 0ull;

        #pragma unroll 1
        for (int chunk = 0; chunk < 2; chunk++) {
            __syncthreads();   // prior chunk's LDS reads done before restage
            // stage es[dd][k] for dd = 0..127 (global d = chunk*128+dd)
            #pragma unroll
            for (int i = 0; i < 8; i++) {
                int idx = i * 512 + tid;
                int k   = idx & 127;
                int d4  = (idx >> 7) * 4;
                float4 v = *(const float4*)&emb[(size_t)(kt * 128 + k) * Dd
                                                + chunk * 128 + d4];
                es[(d4 + 0) * EST + k] = v.x;
                es[(d4 + 1) * EST + k] = v.y;
                es[(d4 + 2) * EST + k] = v.z;
                es[(d4 + 3) * EST + k] = v.w;
            }
            __syncthreads();

            const float* zcol = zs + chunk * 128 * ZST;
            #pragma unroll 2
            for (int dd = 0; dd < 128; dd++) {
                uint64_t zp0, zp1, zp2, zp3;
                lds_v2u64(zp0, zp1, zcol + dd * ZST + r0);
                lds_v2u64(zp2, zp3, zcol + dd * ZST + r0 + 4);
                float e0, e1, e2, e3;
                lds_v4f32(e0, e1, e2, e3, es + dd * EST + k0);
                uint64_t eb0 = dup_x2(e0), eb1 = dup_x2(e1);
                uint64_t eb2 = dup_x2(e2), eb3 = dup_x2(e3);
                fma_x2(acc[0][0], zp0, eb0); fma_x2(acc[1][0], zp1, eb0);
                fma_x2(acc[2][0], zp2, eb0); fma_x2(acc[3][0], zp3, eb0);
                fma_x2(acc[0][1], zp0, eb1); fma_x2(acc[1][1], zp1, eb1);
                fma_x2(acc[2][1], zp2, eb1); fma_x2(acc[3][1], zp3, eb1);
                fma_x2(acc[0][2], zp0, eb2); fma_x2(acc[1][2], zp1, eb2);
                fma_x2(acc[2][2], zp2, eb2); fma_x2(acc[3][2], zp3, eb2);
                fma_x2(acc[0][3], zp0, eb3); fma_x2(acc[1][3], zp1, eb3);
                fma_x2(acc[2][3], zp2, eb3); fma_x2(acc[3][3], zp3, eb3);
            }
        }

        // epilogue: dist + argmin, ascending k (kt asc outer, c asc inner)
        #pragma unroll
        for (int c = 0; c < 4; c++) {
            const int k = kt * 128 + k0 + c;
            const float en = s_en[k];
            #pragma unroll
            for (int p = 0; p < 4; p++) {
                float a0, a1;
                unpack_x2(a0, a1, acc[p][c]);
                const int j0 = 2 * p, j1 = 2 * p + 1;
                float d0 = (zr[j0] + en) - 2.0f * a0;
                float d1 = (zr[j1] + en) - 2.0f * a1;
                if (d0 < bv[j0]) { bv[j0] = d0; bi[j0] = k; }
                if (d1 < bv[j1]) { bv[j1] = d1; bi[j1] = k; }
            }
        }
    }

    // merge across the 32 code-lanes of this row-group; tie -> lower index
    #pragma unroll
    for (int off = 16; off; off >>= 1) {
        #pragma unroll
        for (int j = 0; j < 8; j++) {
            float ov = __shfl_down_sync(0xffffffffu, bv[j], off);
            int   oi = __shfl_down_sync(0xffffffffu, bi[j], off);
            if (ov < bv[j] || (ov == bv[j] && oi < bi[j])) {
                bv[j] = ov; bi[j] = oi;
            }
        }
    }
    if (lane == 0) {
        #pragma unroll
        for (int j = 0; j < 8; j++)
            g_idx[row0 + r0 + j] = bi[j];
    }
}

// ---------------------------------------------------------------------------
// gather: z_q_st = embedding[idx] scattered to (B,D,L); fused sum((z-q)^2)
// ---------------------------------------------------------------------------
__global__ void __launch_bounds__(256)
vq_gather_kernel(const float* __restrict__ z, const float* __restrict__ emb,
                 float* __restrict__ out) {
    __shared__ float q[TL][Dd + 1];
    __shared__ int   idxs[TL];
    __shared__ float wsum[8];

    const int tid = threadIdx.x;
    const int t   = blockIdx.x;
    const int b   = t >> 7;
    const int l0  = (t & 127) * TL;
    const int rbase = b * Ll + l0;

    if (tid < TL) idxs[tid] = g_idx[rbase + tid];
    __syncthreads();

    for (int i = tid; i < TL * Dd; i += 256) {
        int r = i >> 8, d = i & 255;
        q[r][d] = emb[(size_t)idxs[r] * Dd + d];
    }
    __syncthreads();

    float lsum = 0.f;
    const float* zb = z   + (size_t)b * Dd * Ll + l0;
    float*       ob = out + (size_t)b * Dd * Ll + l0;
    for (int i = tid; i < Dd * TL; i += 256) {
        int d = i >> 5, lr = i & 31;
        float v  = q[lr][d];
        float ze = zb[(size_t)d * Ll + lr];
        ob[(size_t)d * Ll + lr] = v;
        float df = ze - v;
        lsum += df * df;
    }

    #pragma unroll
    for (int off = 16; off; off >>= 1)
        lsum += __shfl_xor_sync(0xffffffffu, lsum, off);
    if ((tid & 31) == 0) wsum[tid >> 5] = lsum;
    __syncthreads();
    if (tid == 0) {
        float s = 0.f;
        #pragma unroll
        for (int w = 0; w < 8; w++) s += wsum[w];
        atomicAdd(&g_acc, (double)s);
    }
}

// ---------------------------------------------------------------------------
__global__ void vq_tail_kernel(float* __restrict__ out) {
    int i = blockIdx.x * blockDim.x + threadIdx.x;
    if (i < Nn) out[NDL + i] = (float)g_idx[i];
}

__global__ void vq_loss_kernel(float* __restrict__ out) {
    double mse = g_acc / (double)NDL;
    out[NDL + Nn + 0] = (float)(1.25 * mse);
    out[NDL + Nn + 1] = (float)mse;
    out[NDL + Nn + 2] = (float)(0.25 * mse);
}

// ---------------------------------------------------------------------------
extern "C" void kernel_launch(void* const* d_in, const int* in_sizes, int n_in,
                              void* d_out, int out_size) {
    const float* z   = (const float*)d_in[0];
    const float* emb = (const float*)d_in[1];
    if (n_in >= 2 && in_sizes[0] == Kk * Dd && in_sizes[1] == NDL) {
        emb = (const float*)d_in[0];
        z   = (const float*)d_in[1];
    }
    float* out = (float*)d_out;

    cudaFuncSetAttribute(vq_scores_f32x2,
                         cudaFuncAttributeMaxDynamicSharedMemorySize, SM_TOTAL);

    vq_prep_kernel<<<(Kk + 255) / 256, 256>>>(emb);
    vq_scores_f32x2<<<Nn / 128, 512, SM_TOTAL>>>(z, emb);
    vq_gather_kernel<<<Nn / TL, 256>>>(z, emb, out);
    if (out_size >= NDL + Nn)
        vq_tail_kernel<<<(Nn + 255) / 256, 256>>>(out);
    if (out_size >= NDL + Nn + 3)
        vq_loss_kernel<<<1, 1>>>(out);
}